// round 4
// baseline (speedup 1.0000x reference)
#include <cuda_runtime.h>
#include <cuda_bf16.h>
#include <math.h>
#include <stdint.h>

#define BB 8
#define NN 100
#define DD 768
#define HH 768
#define TH 24
#define TT 577
#define IMGF 384.0f
#define M_ROWS 800

// Scratch (device globals: allocation-free, graph-capture safe)
__device__ float g_rowsum[BB * TH * TH * DD];   // row-prefix sums
__device__ __nv_bfloat16 g_pA[M_ROWS * DD];     // pooled, bf16
__device__ __nv_bfloat16 g_pW[2 * DD * HH];     // W1, bf16
__device__ float g_ha[M_ROWS * HH];             // pooled@W1[:D] + b1
__device__ float g_hb[M_ROWS * HH];             // pooled@W1[D:]

// ---------------------------------------------------------------------------
// Kernel A (fused): blocks 0..191 compute row prefix sums of the feature map;
// blocks 192..575 convert W1 fp32 -> bf16.  768 threads each.
// ---------------------------------------------------------------------------
__global__ void prep_kernel(const float* __restrict__ tokens,
                            const float* __restrict__ W1) {
    if (blockIdx.x < BB * TH) {
        int by = blockIdx.x;            // 0..191
        int b = by / TH, y = by % TH;
        int t = threadIdx.x;
        const float* src = tokens + ((size_t)b * TT + 1 + y * TH) * DD + t;
        float* dst = g_rowsum + ((size_t)(b * TH + y) * TH) * DD + t;
        float run = 0.f;
        #pragma unroll
        for (int x = 0; x < TH; ++x) {
            run += src[(size_t)x * DD];
            dst[(size_t)x * DD] = run;
        }
    } else {
        // W1 convert: 2*768*768 = 1,179,648 floats = 294,912 float4
        int i = (blockIdx.x - BB * TH) * 768 + threadIdx.x;   // 0..294911
        float4 v = ((const float4*)W1)[i];
        __nv_bfloat162* dst = (__nv_bfloat162*)(g_pW + (size_t)i * 4);
        dst[0] = __floats2bfloat162_rn(v.x, v.y);
        dst[1] = __floats2bfloat162_rn(v.z, v.w);
    }
}

// ---------------------------------------------------------------------------
// Kernel B: ROI pool from row-prefix sums -> pooled bf16.
// Replicates the reference's int-truncation chain exactly in fp32.
// ---------------------------------------------------------------------------
__device__ __forceinline__ int to_patch(float v) {
    float pix = floorf(v * IMGF);
    return (int)floorf(pix / IMGF * (float)TH);
}

__global__ void pool_gather_kernel(const float* __restrict__ boxes) {
    int bn = blockIdx.x;            // 0..799
    int b = bn / NN;
    const float* box = boxes + (size_t)bn * 4;

    int px1 = min(max(to_patch(box[0]), 0), TH - 1);
    int py1 = min(max(to_patch(box[1]), 0), TH - 1);
    int px2 = min(max(to_patch(box[2]), 1), TH);
    int py2 = min(max(to_patch(box[3]), 1), TH);
    if (px2 <= px1) px2 = px1 + 1;
    if (py2 <= py1) py2 = py1 + 1;

    float inv = 1.0f / (float)((px2 - px1) * (py2 - py1));

    int t = threadIdx.x;
    const float* base = g_rowsum + (size_t)(b * TH * TH) * DD + t;
    float s = 0.f;
    for (int y = py1; y < py2; ++y) {
        const float* row = base + (size_t)(y * TH) * DD;
        float hi = row[(size_t)(px2 - 1) * DD];
        float lo = (px1 > 0) ? row[(size_t)(px1 - 1) * DD] : 0.f;
        s += hi - lo;
    }
    g_pA[(size_t)bn * DD + t] = __float2bfloat16_rn(s * inv);
}

// ---------------------------------------------------------------------------
// bf16 tensor-core GEMM: C[800,1536] = pooled[800,768] @ W[768,1536]
// (halves of W1 fused via n-block; cols 0-767 -> g_ha (+b1), 768-1535 -> g_hb).
// CTA tile 64x64, BK=32, 8 warps, mma.m16n8k16.bf16, padded-stride smem.
// ---------------------------------------------------------------------------
#define ASTR 40
#define BSTR 72

__global__ __launch_bounds__(256) void gemm_bf16_kernel(const float* __restrict__ b1) {
    __shared__ __nv_bfloat16 As[2][64 * ASTR];
    __shared__ __nv_bfloat16 Bs[2][32 * BSTR];

    int tid = threadIdx.x;
    int lane = tid & 31, wid = tid >> 5;
    int m0 = blockIdx.y * 64;
    int nblk = blockIdx.x;                  // 0..23
    int half = (nblk >= 12);
    int n_in0 = nblk * 64 - half * 768;     // 0..704 within half
    const __nv_bfloat16* Bg = g_pW + (size_t)half * DD * HH;

    int a_r = tid >> 2, a_c = (tid & 3) * 8;
    int b_r = tid >> 3, b_c = (tid & 7) * 8;
    int wm = (wid & 3) * 16, wn = (wid >> 2) * 32;

    float d[4][4];
    #pragma unroll
    for (int j = 0; j < 4; ++j)
        #pragma unroll
        for (int c = 0; c < 4; ++c) d[j][c] = 0.f;

    const uint4 z4 = make_uint4(0, 0, 0, 0);
    uint4 ra, rb;

    {
        int gr = m0 + a_r;
        ra = (gr < M_ROWS) ? *(const uint4*)(g_pA + (size_t)gr * DD + a_c) : z4;
        rb = *(const uint4*)(Bg + (size_t)b_r * HH + n_in0 + b_c);
        *(uint4*)(As[0] + a_r * ASTR + a_c) = ra;
        *(uint4*)(Bs[0] + b_r * BSTR + b_c) = rb;
    }
    __syncthreads();

    int lrow = (lane & 7) + ((lane >> 3) & 1) * 8;
    int lk8  = (lane >> 4) * 8;

    for (int it = 0; it < 24; ++it) {
        int buf = it & 1;
        if (it < 23) {
            int k0 = (it + 1) * 32;
            int gr = m0 + a_r;
            ra = (gr < M_ROWS) ? *(const uint4*)(g_pA + (size_t)gr * DD + k0 + a_c) : z4;
            rb = *(const uint4*)(Bg + (size_t)(k0 + b_r) * HH + n_in0 + b_c);
        }
        uint32_t abase = (uint32_t)__cvta_generic_to_shared(&As[buf][0]);
        uint32_t bbase = (uint32_t)__cvta_generic_to_shared(&Bs[buf][0]);

        #pragma unroll
        for (int kq = 0; kq < 32; kq += 16) {
            uint32_t a0, a1, a2, a3;
            uint32_t aaddr = abase + (uint32_t)(((wm + lrow) * ASTR + kq + lk8) * 2);
            asm volatile("ldmatrix.sync.aligned.m8n8.x4.shared.b16 {%0,%1,%2,%3}, [%4];"
                         : "=r"(a0), "=r"(a1), "=r"(a2), "=r"(a3) : "r"(aaddr));
            #pragma unroll
            for (int h = 0; h < 2; ++h) {
                uint32_t b0, b1r, b2, b3;
                uint32_t baddr = bbase + (uint32_t)(((kq + lrow) * BSTR + wn + h * 16 + lk8) * 2);
                asm volatile("ldmatrix.sync.aligned.m8n8.x4.trans.shared.b16 {%0,%1,%2,%3}, [%4];"
                             : "=r"(b0), "=r"(b1r), "=r"(b2), "=r"(b3) : "r"(baddr));
                asm volatile("mma.sync.aligned.m16n8k16.row.col.f32.bf16.bf16.f32 "
                             "{%0,%1,%2,%3}, {%4,%5,%6,%7}, {%8,%9}, {%0,%1,%2,%3};"
                             : "+f"(d[2*h][0]), "+f"(d[2*h][1]), "+f"(d[2*h][2]), "+f"(d[2*h][3])
                             : "r"(a0), "r"(a1), "r"(a2), "r"(a3), "r"(b0), "r"(b1r));
                asm volatile("mma.sync.aligned.m16n8k16.row.col.f32.bf16.bf16.f32 "
                             "{%0,%1,%2,%3}, {%4,%5,%6,%7}, {%8,%9}, {%0,%1,%2,%3};"
                             : "+f"(d[2*h+1][0]), "+f"(d[2*h+1][1]), "+f"(d[2*h+1][2]), "+f"(d[2*h+1][3])
                             : "r"(a0), "r"(a1), "r"(a2), "r"(a3), "r"(b2), "r"(b3));
            }
        }
        if (it < 23) {
            *(uint4*)(As[buf ^ 1] + a_r * ASTR + a_c) = ra;
            *(uint4*)(Bs[buf ^ 1] + b_r * BSTR + b_c) = rb;
            __syncthreads();
        }
    }

    // epilogue: ha half gets +b1 fused
    float* dst = half ? g_hb : g_ha;
    int row0 = m0 + wm + (lane >> 2);
    #pragma unroll
    for (int j = 0; j < 4; ++j) {
        int col = n_in0 + wn + j * 8 + (lane & 3) * 2;
        float bx = 0.f, by = 0.f;
        if (!half) { bx = b1[col]; by = b1[col + 1]; }
        if (row0 < M_ROWS) {
            float2 v = make_float2(d[j][0] + bx, d[j][1] + by);
            *(float2*)(dst + (size_t)row0 * HH + col) = v;
        }
        if (row0 + 8 < M_ROWS) {
            float2 v = make_float2(d[j][2] + bx, d[j][3] + by);
            *(float2*)(dst + (size_t)(row0 + 8) * HH + col) = v;
        }
    }
}

// ---------------------------------------------------------------------------
// Pairwise relu-MLP dot: block = 4 i-rows x all 100 j, 512 threads.
// Each warp: il = warp>>2, j stride 4 (warp&3).
// ---------------------------------------------------------------------------
#define TI 4

__global__ __launch_bounds__(512) void pairwise_kernel(const float* __restrict__ W2,
                                                       const float* __restrict__ b2,
                                                       float* __restrict__ out) {
    int i0 = blockIdx.x * TI;
    int b = blockIdx.y;

    __shared__ float sHa[TI][HH];
    __shared__ float sW2[HH];

    int t = threadIdx.x;                 // 512
    for (int idx = t; idx < TI * HH; idx += 512) {
        int il = idx / HH, h = idx % HH;
        sHa[il][h] = g_ha[((size_t)b * NN + i0 + il) * HH + h];   // b1 pre-fused
    }
    for (int h = t; h < HH; h += 512) sW2[h] = W2[h];
    __syncthreads();

    float bias2 = b2[0];
    int warp = t >> 5, lane = t & 31;
    int il = warp >> 2;                  // 0..3
    int jpar = warp & 3;                 // 0..3

    const float4* sHa4 = (const float4*)&sHa[il][0];
    const float4* sW24 = (const float4*)&sW2[0];

    for (int j = jpar; j < NN; j += 4) {
        const float4* hb4 = (const float4*)(g_hb + ((size_t)b * NN + j) * HH);
        float acc = 0.f;
        #pragma unroll
        for (int it = 0; it < HH / (32 * 4); ++it) {    // 6
            int q = lane + 32 * it;
            float4 hv = hb4[q];
            float4 av = sHa4[q];
            float4 wv = sW24[q];
            acc += fmaxf(av.x + hv.x, 0.f) * wv.x;
            acc += fmaxf(av.y + hv.y, 0.f) * wv.y;
            acc += fmaxf(av.z + hv.z, 0.f) * wv.z;
            acc += fmaxf(av.w + hv.w, 0.f) * wv.w;
        }
        #pragma unroll
        for (int o = 16; o > 0; o >>= 1)
            acc += __shfl_xor_sync(0xffffffffu, acc, o);
        if (lane == 0) {
            float x = acc + bias2;
            out[((size_t)b * NN + i0 + il) * NN + j] = 1.f / (1.f + expf(-x));
        }
    }
}

// ---------------------------------------------------------------------------
// Launch
// ---------------------------------------------------------------------------
extern "C" void kernel_launch(void* const* d_in, const int* in_sizes, int n_in,
                              void* d_out, int out_size) {
    const float* patch_tokens = (const float*)d_in[0];  // [8,577,768]
    const float* boxes        = (const float*)d_in[1];  // [8,100,4]
    const float* W1           = (const float*)d_in[2];  // [1536,768]
    const float* b1           = (const float*)d_in[3];  // [768]
    const float* W2           = (const float*)d_in[4];  // [768,1]
    const float* b2           = (const float*)d_in[5];  // [1]
    float* out = (float*)d_out;                         // [8,100,100]

    prep_kernel<<<BB * TH + 384, DD>>>(patch_tokens, W1);   // 576 blocks
    pool_gather_kernel<<<M_ROWS, DD>>>(boxes);

    dim3 ggrid(24, 13);
    gemm_bf16_kernel<<<ggrid, 256>>>(b1);

    dim3 pgrid(NN / TI, BB);                                // (25, 8)
    pairwise_kernel<<<pgrid, 512>>>(W2, b2, out);
}

// round 5
// speedup vs baseline: 1.7939x; 1.7939x over previous
#include <cuda_runtime.h>
#include <cuda_bf16.h>
#include <math.h>
#include <stdint.h>

#define BB 8
#define NN 100
#define DD 768
#define HH 768
#define TH 24
#define TT 577
#define IMGF 384.0f
#define M_ROWS 800

// Scratch (device globals: allocation-free, graph-capture safe)
__device__ float g_rowsum[BB * TH * TH * DD];   // row-prefix sums
__device__ __nv_bfloat16 g_pA[M_ROWS * DD];     // pooled, bf16
__device__ __nv_bfloat16 g_pW[2 * DD * HH];     // W1, bf16
__device__ float g_ha[M_ROWS * HH];             // pooled@W1[:D] + b1
__device__ float g_hb[M_ROWS * HH];             // pooled@W1[D:]

// ---------------------------------------------------------------------------
// Kernel A (fused): blocks 0..191 row-prefix-sum the feature map;
// blocks 192..575 convert W1 fp32 -> bf16.
// ---------------------------------------------------------------------------
__global__ void prep_kernel(const float* __restrict__ tokens,
                            const float* __restrict__ W1) {
    if (blockIdx.x < BB * TH) {
        int by = blockIdx.x;
        int b = by / TH, y = by % TH;
        int t = threadIdx.x;
        const float* src = tokens + ((size_t)b * TT + 1 + y * TH) * DD + t;
        float* dst = g_rowsum + ((size_t)(b * TH + y) * TH) * DD + t;
        float run = 0.f;
        #pragma unroll
        for (int x = 0; x < TH; ++x) {
            run += src[(size_t)x * DD];
            dst[(size_t)x * DD] = run;
        }
    } else {
        int i = (blockIdx.x - BB * TH) * 768 + threadIdx.x;   // 0..294911 float4s
        float4 v = ((const float4*)W1)[i];
        __nv_bfloat162* dst = (__nv_bfloat162*)(g_pW + (size_t)i * 4);
        dst[0] = __floats2bfloat162_rn(v.x, v.y);
        dst[1] = __floats2bfloat162_rn(v.z, v.w);
    }
}

// ---------------------------------------------------------------------------
// Kernel B: ROI pool from row-prefix sums -> pooled bf16.
// Replicates the reference's int-truncation chain exactly in fp32.
// ---------------------------------------------------------------------------
__device__ __forceinline__ int to_patch(float v) {
    float pix = floorf(v * IMGF);
    return (int)floorf(pix / IMGF * (float)TH);
}

__global__ void pool_gather_kernel(const float* __restrict__ boxes) {
    int bn = blockIdx.x;
    int b = bn / NN;
    const float* box = boxes + (size_t)bn * 4;

    int px1 = min(max(to_patch(box[0]), 0), TH - 1);
    int py1 = min(max(to_patch(box[1]), 0), TH - 1);
    int px2 = min(max(to_patch(box[2]), 1), TH);
    int py2 = min(max(to_patch(box[3]), 1), TH);
    if (px2 <= px1) px2 = px1 + 1;
    if (py2 <= py1) py2 = py1 + 1;

    float inv = 1.0f / (float)((px2 - px1) * (py2 - py1));

    int t = threadIdx.x;
    const float* base = g_rowsum + (size_t)(b * TH * TH) * DD + t;
    float s = 0.f;
    for (int y = py1; y < py2; ++y) {
        const float* row = base + (size_t)(y * TH) * DD;
        float hi = row[(size_t)(px2 - 1) * DD];
        float lo = (px1 > 0) ? row[(size_t)(px1 - 1) * DD] : 0.f;
        s += hi - lo;
    }
    g_pA[(size_t)bn * DD + t] = __float2bfloat16_rn(s * inv);
}

// ---------------------------------------------------------------------------
// bf16 tensor-core GEMM: C[800,1536] = pooled[800,768] @ W[768,1536]
// cols 0-767 -> g_ha (+b1 fused), 768-1535 -> g_hb.
// ---------------------------------------------------------------------------
#define ASTR 40
#define BSTR 72

__global__ __launch_bounds__(256) void gemm_bf16_kernel(const float* __restrict__ b1) {
    __shared__ __nv_bfloat16 As[2][64 * ASTR];
    __shared__ __nv_bfloat16 Bs[2][32 * BSTR];

    int tid = threadIdx.x;
    int lane = tid & 31, wid = tid >> 5;
    int m0 = blockIdx.y * 64;
    int nblk = blockIdx.x;
    int half = (nblk >= 12);
    int n_in0 = nblk * 64 - half * 768;
    const __nv_bfloat16* Bg = g_pW + (size_t)half * DD * HH;

    int a_r = tid >> 2, a_c = (tid & 3) * 8;
    int b_r = tid >> 3, b_c = (tid & 7) * 8;
    int wm = (wid & 3) * 16, wn = (wid >> 2) * 32;

    float d[4][4];
    #pragma unroll
    for (int j = 0; j < 4; ++j)
        #pragma unroll
        for (int c = 0; c < 4; ++c) d[j][c] = 0.f;

    const uint4 z4 = make_uint4(0, 0, 0, 0);
    uint4 ra, rb;

    {
        int gr = m0 + a_r;
        ra = (gr < M_ROWS) ? *(const uint4*)(g_pA + (size_t)gr * DD + a_c) : z4;
        rb = *(const uint4*)(Bg + (size_t)b_r * HH + n_in0 + b_c);
        *(uint4*)(As[0] + a_r * ASTR + a_c) = ra;
        *(uint4*)(Bs[0] + b_r * BSTR + b_c) = rb;
    }
    __syncthreads();

    int lrow = (lane & 7) + ((lane >> 3) & 1) * 8;
    int lk8  = (lane >> 4) * 8;

    for (int it = 0; it < 24; ++it) {
        int buf = it & 1;
        if (it < 23) {
            int k0 = (it + 1) * 32;
            int gr = m0 + a_r;
            ra = (gr < M_ROWS) ? *(const uint4*)(g_pA + (size_t)gr * DD + k0 + a_c) : z4;
            rb = *(const uint4*)(Bg + (size_t)(k0 + b_r) * HH + n_in0 + b_c);
        }
        uint32_t abase = (uint32_t)__cvta_generic_to_shared(&As[buf][0]);
        uint32_t bbase = (uint32_t)__cvta_generic_to_shared(&Bs[buf][0]);

        #pragma unroll
        for (int kq = 0; kq < 32; kq += 16) {
            uint32_t a0, a1, a2, a3;
            uint32_t aaddr = abase + (uint32_t)(((wm + lrow) * ASTR + kq + lk8) * 2);
            asm volatile("ldmatrix.sync.aligned.m8n8.x4.shared.b16 {%0,%1,%2,%3}, [%4];"
                         : "=r"(a0), "=r"(a1), "=r"(a2), "=r"(a3) : "r"(aaddr));
            #pragma unroll
            for (int h = 0; h < 2; ++h) {
                uint32_t b0, b1r, b2, b3;
                uint32_t baddr = bbase + (uint32_t)(((kq + lrow) * BSTR + wn + h * 16 + lk8) * 2);
                asm volatile("ldmatrix.sync.aligned.m8n8.x4.trans.shared.b16 {%0,%1,%2,%3}, [%4];"
                             : "=r"(b0), "=r"(b1r), "=r"(b2), "=r"(b3) : "r"(baddr));
                asm volatile("mma.sync.aligned.m16n8k16.row.col.f32.bf16.bf16.f32 "
                             "{%0,%1,%2,%3}, {%4,%5,%6,%7}, {%8,%9}, {%0,%1,%2,%3};"
                             : "+f"(d[2*h][0]), "+f"(d[2*h][1]), "+f"(d[2*h][2]), "+f"(d[2*h][3])
                             : "r"(a0), "r"(a1), "r"(a2), "r"(a3), "r"(b0), "r"(b1r));
                asm volatile("mma.sync.aligned.m16n8k16.row.col.f32.bf16.bf16.f32 "
                             "{%0,%1,%2,%3}, {%4,%5,%6,%7}, {%8,%9}, {%0,%1,%2,%3};"
                             : "+f"(d[2*h+1][0]), "+f"(d[2*h+1][1]), "+f"(d[2*h+1][2]), "+f"(d[2*h+1][3])
                             : "r"(a0), "r"(a1), "r"(a2), "r"(a3), "r"(b2), "r"(b3));
            }
        }
        if (it < 23) {
            *(uint4*)(As[buf ^ 1] + a_r * ASTR + a_c) = ra;
            *(uint4*)(Bs[buf ^ 1] + b_r * BSTR + b_c) = rb;
            __syncthreads();
        }
    }

    float* dst = half ? g_hb : g_ha;
    int row0 = m0 + wm + (lane >> 2);
    #pragma unroll
    for (int j = 0; j < 4; ++j) {
        int col = n_in0 + wn + j * 8 + (lane & 3) * 2;
        float bx = 0.f, by = 0.f;
        if (!half) { bx = b1[col]; by = b1[col + 1]; }
        if (row0 < M_ROWS) {
            float2 v = make_float2(d[j][0] + bx, d[j][1] + by);
            *(float2*)(dst + (size_t)row0 * HH + col) = v;
        }
        if (row0 + 8 < M_ROWS) {
            float2 v = make_float2(d[j][2] + bx, d[j][3] + by);
            *(float2*)(dst + (size_t)(row0 + 8) * HH + col) = v;
        }
    }
}

// ---------------------------------------------------------------------------
// Pairwise relu-MLP v3: output-stationary. Block = 32i x 32j tile,
// 256 threads (16x16), each owns 2x2 outputs. h chunked 64-wide into
// transposed smem (stride 34: float2-aligned, conflict-free inner reads).
// No shuffles, no gmem in inner loop, 4 independent acc chains per thread.
// ---------------------------------------------------------------------------
#define CH 64
#define PSTR 34

__global__ __launch_bounds__(256) void pairwise_kernel(const float* __restrict__ W2,
                                                       const float* __restrict__ b2,
                                                       float* __restrict__ out) {
    __shared__ float sA[CH][PSTR];
    __shared__ float sB[CH][PSTR];
    __shared__ float sW[CH];

    int b = blockIdx.y;
    int i0 = (blockIdx.x >> 2) * 32;     // 0,32,64,96
    int j0 = (blockIdx.x & 3) * 32;

    int tid = threadIdx.x;
    int ty = tid >> 4, tx = tid & 15;

    float acc[2][2] = {{0.f, 0.f}, {0.f, 0.f}};

    const float* haB = g_ha + (size_t)b * NN * HH;
    const float* hbB = g_hb + (size_t)b * NN * HH;

    for (int h0 = 0; h0 < HH; h0 += CH) {
        // fill: 32 rows x 64 h, 8 elements per thread per array
        #pragma unroll
        for (int k = 0; k < 8; ++k) {
            int idx = tid + k * 256;            // 0..2047
            int il = idx >> 6;                  // 0..31
            int hl = idx & 63;                  // 0..63
            int gi = min(i0 + il, NN - 1);
            int gj = min(j0 + il, NN - 1);
            sA[hl][il] = haB[(size_t)gi * HH + h0 + hl];
            sB[hl][il] = hbB[(size_t)gj * HH + h0 + hl];
        }
        if (tid < CH) sW[tid] = W2[h0 + tid];
        __syncthreads();

        #pragma unroll 8
        for (int h = 0; h < CH; ++h) {
            float2 av = *(const float2*)&sA[h][2 * ty];
            float2 bv = *(const float2*)&sB[h][2 * tx];
            float w = sW[h];
            acc[0][0] += fmaxf(av.x + bv.x, 0.f) * w;
            acc[0][1] += fmaxf(av.x + bv.y, 0.f) * w;
            acc[1][0] += fmaxf(av.y + bv.x, 0.f) * w;
            acc[1][1] += fmaxf(av.y + bv.y, 0.f) * w;
        }
        __syncthreads();
    }

    float bias2 = b2[0];
    #pragma unroll
    for (int r = 0; r < 2; ++r) {
        int i = i0 + 2 * ty + r;
        if (i >= NN) continue;
        #pragma unroll
        for (int c = 0; c < 2; ++c) {
            int j = j0 + 2 * tx + c;
            if (j >= NN) continue;
            float x = acc[r][c] + bias2;
            out[((size_t)b * NN + i) * NN + j] = 1.f / (1.f + expf(-x));
        }
    }
}

// ---------------------------------------------------------------------------
// Launch
// ---------------------------------------------------------------------------
extern "C" void kernel_launch(void* const* d_in, const int* in_sizes, int n_in,
                              void* d_out, int out_size) {
    const float* patch_tokens = (const float*)d_in[0];  // [8,577,768]
    const float* boxes        = (const float*)d_in[1];  // [8,100,4]
    const float* W1           = (const float*)d_in[2];  // [1536,768]
    const float* b1           = (const float*)d_in[3];  // [768]
    const float* W2           = (const float*)d_in[4];  // [768,1]
    const float* b2           = (const float*)d_in[5];  // [1]
    float* out = (float*)d_out;                         // [8,100,100]

    prep_kernel<<<BB * TH + 384, DD>>>(patch_tokens, W1);   // 576 blocks
    pool_gather_kernel<<<M_ROWS, DD>>>(boxes);

    dim3 ggrid(24, 13);
    gemm_bf16_kernel<<<ggrid, 256>>>(b1);

    dim3 pgrid(16, BB);                                     // 128 blocks
    pairwise_kernel<<<pgrid, 256>>>(W2, b2, out);
}

// round 6
// speedup vs baseline: 2.1244x; 1.1842x over previous
#include <cuda_runtime.h>
#include <cuda_bf16.h>
#include <math.h>
#include <stdint.h>

#define BB 8
#define NN 100
#define DD 768
#define HH 768
#define TH 24
#define TT 577
#define IMGF 384.0f
#define M_ROWS 800
#define SPLIT 8
#define HSUB (HH / SPLIT)    // 96

// Scratch (device globals: allocation-free, graph-capture safe)
__device__ float g_rowsum[BB * TH * TH * DD];
__device__ __nv_bfloat16 g_pA[M_ROWS * DD];
__device__ __nv_bfloat16 g_pW[2 * DD * HH];
__device__ float g_ha[M_ROWS * HH];                 // pooled@W1[:D] + b1
__device__ float g_hb[M_ROWS * HH];                 // pooled@W1[D:]
__device__ float g_part[SPLIT * BB * 128 * 128];    // pairwise partials, 4.2MB

// ---------------------------------------------------------------------------
// Kernel A (fused): blocks 0..191 row-prefix-sum the feature map;
// blocks 192..575 convert W1 fp32 -> bf16.
// ---------------------------------------------------------------------------
__global__ void prep_kernel(const float* __restrict__ tokens,
                            const float* __restrict__ W1) {
    if (blockIdx.x < BB * TH) {
        int by = blockIdx.x;
        int b = by / TH, y = by % TH;
        int t = threadIdx.x;
        const float* src = tokens + ((size_t)b * TT + 1 + y * TH) * DD + t;
        float* dst = g_rowsum + ((size_t)(b * TH + y) * TH) * DD + t;
        float run = 0.f;
        #pragma unroll
        for (int x = 0; x < TH; ++x) {
            run += src[(size_t)x * DD];
            dst[(size_t)x * DD] = run;
        }
    } else {
        int i = (blockIdx.x - BB * TH) * 768 + threadIdx.x;
        float4 v = ((const float4*)W1)[i];
        __nv_bfloat162* dst = (__nv_bfloat162*)(g_pW + (size_t)i * 4);
        dst[0] = __floats2bfloat162_rn(v.x, v.y);
        dst[1] = __floats2bfloat162_rn(v.z, v.w);
    }
}

// ---------------------------------------------------------------------------
// Kernel B: ROI pool from row-prefix sums -> pooled bf16.
// ---------------------------------------------------------------------------
__device__ __forceinline__ int to_patch(float v) {
    float pix = floorf(v * IMGF);
    return (int)floorf(pix / IMGF * (float)TH);
}

__global__ void pool_gather_kernel(const float* __restrict__ boxes) {
    int bn = blockIdx.x;
    int b = bn / NN;
    const float* box = boxes + (size_t)bn * 4;

    int px1 = min(max(to_patch(box[0]), 0), TH - 1);
    int py1 = min(max(to_patch(box[1]), 0), TH - 1);
    int px2 = min(max(to_patch(box[2]), 1), TH);
    int py2 = min(max(to_patch(box[3]), 1), TH);
    if (px2 <= px1) px2 = px1 + 1;
    if (py2 <= py1) py2 = py1 + 1;

    float inv = 1.0f / (float)((px2 - px1) * (py2 - py1));

    int t = threadIdx.x;
    const float* base = g_rowsum + (size_t)(b * TH * TH) * DD + t;
    float s = 0.f;
    for (int y = py1; y < py2; ++y) {
        const float* row = base + (size_t)(y * TH) * DD;
        float hi = row[(size_t)(px2 - 1) * DD];
        float lo = (px1 > 0) ? row[(size_t)(px1 - 1) * DD] : 0.f;
        s += hi - lo;
    }
    g_pA[(size_t)bn * DD + t] = __float2bfloat16_rn(s * inv);
}

// ---------------------------------------------------------------------------
// bf16 tensor-core GEMM: C[800,1536] = pooled[800,768] @ W[768,1536]
// cols 0-767 -> g_ha (+b1 fused), 768-1535 -> g_hb.
// ---------------------------------------------------------------------------
#define ASTR 40
#define BSTR 72

__global__ __launch_bounds__(256) void gemm_bf16_kernel(const float* __restrict__ b1) {
    __shared__ __nv_bfloat16 As[2][64 * ASTR];
    __shared__ __nv_bfloat16 Bs[2][32 * BSTR];

    int tid = threadIdx.x;
    int lane = tid & 31, wid = tid >> 5;
    int m0 = blockIdx.y * 64;
    int nblk = blockIdx.x;
    int half = (nblk >= 12);
    int n_in0 = nblk * 64 - half * 768;
    const __nv_bfloat16* Bg = g_pW + (size_t)half * DD * HH;

    int a_r = tid >> 2, a_c = (tid & 3) * 8;
    int b_r = tid >> 3, b_c = (tid & 7) * 8;
    int wm = (wid & 3) * 16, wn = (wid >> 2) * 32;

    float d[4][4];
    #pragma unroll
    for (int j = 0; j < 4; ++j)
        #pragma unroll
        for (int c = 0; c < 4; ++c) d[j][c] = 0.f;

    const uint4 z4 = make_uint4(0, 0, 0, 0);
    uint4 ra, rb;

    {
        int gr = m0 + a_r;
        ra = (gr < M_ROWS) ? *(const uint4*)(g_pA + (size_t)gr * DD + a_c) : z4;
        rb = *(const uint4*)(Bg + (size_t)b_r * HH + n_in0 + b_c);
        *(uint4*)(As[0] + a_r * ASTR + a_c) = ra;
        *(uint4*)(Bs[0] + b_r * BSTR + b_c) = rb;
    }
    __syncthreads();

    int lrow = (lane & 7) + ((lane >> 3) & 1) * 8;
    int lk8  = (lane >> 4) * 8;

    for (int it = 0; it < 24; ++it) {
        int buf = it & 1;
        if (it < 23) {
            int k0 = (it + 1) * 32;
            int gr = m0 + a_r;
            ra = (gr < M_ROWS) ? *(const uint4*)(g_pA + (size_t)gr * DD + k0 + a_c) : z4;
            rb = *(const uint4*)(Bg + (size_t)(k0 + b_r) * HH + n_in0 + b_c);
        }
        uint32_t abase = (uint32_t)__cvta_generic_to_shared(&As[buf][0]);
        uint32_t bbase = (uint32_t)__cvta_generic_to_shared(&Bs[buf][0]);

        #pragma unroll
        for (int kq = 0; kq < 32; kq += 16) {
            uint32_t a0, a1, a2, a3;
            uint32_t aaddr = abase + (uint32_t)(((wm + lrow) * ASTR + kq + lk8) * 2);
            asm volatile("ldmatrix.sync.aligned.m8n8.x4.shared.b16 {%0,%1,%2,%3}, [%4];"
                         : "=r"(a0), "=r"(a1), "=r"(a2), "=r"(a3) : "r"(aaddr));
            #pragma unroll
            for (int h = 0; h < 2; ++h) {
                uint32_t b0, b1r, b2, b3;
                uint32_t baddr = bbase + (uint32_t)(((kq + lrow) * BSTR + wn + h * 16 + lk8) * 2);
                asm volatile("ldmatrix.sync.aligned.m8n8.x4.trans.shared.b16 {%0,%1,%2,%3}, [%4];"
                             : "=r"(b0), "=r"(b1r), "=r"(b2), "=r"(b3) : "r"(baddr));
                asm volatile("mma.sync.aligned.m16n8k16.row.col.f32.bf16.bf16.f32 "
                             "{%0,%1,%2,%3}, {%4,%5,%6,%7}, {%8,%9}, {%0,%1,%2,%3};"
                             : "+f"(d[2*h][0]), "+f"(d[2*h][1]), "+f"(d[2*h][2]), "+f"(d[2*h][3])
                             : "r"(a0), "r"(a1), "r"(a2), "r"(a3), "r"(b0), "r"(b1r));
                asm volatile("mma.sync.aligned.m16n8k16.row.col.f32.bf16.bf16.f32 "
                             "{%0,%1,%2,%3}, {%4,%5,%6,%7}, {%8,%9}, {%0,%1,%2,%3};"
                             : "+f"(d[2*h+1][0]), "+f"(d[2*h+1][1]), "+f"(d[2*h+1][2]), "+f"(d[2*h+1][3])
                             : "r"(a0), "r"(a1), "r"(a2), "r"(a3), "r"(b2), "r"(b3));
            }
        }
        if (it < 23) {
            *(uint4*)(As[buf ^ 1] + a_r * ASTR + a_c) = ra;
            *(uint4*)(Bs[buf ^ 1] + b_r * BSTR + b_c) = rb;
            __syncthreads();
        }
    }

    float* dst = half ? g_hb : g_ha;
    int row0 = m0 + wm + (lane >> 2);
    #pragma unroll
    for (int j = 0; j < 4; ++j) {
        int col = n_in0 + wn + j * 8 + (lane & 3) * 2;
        float bx = 0.f, by = 0.f;
        if (!half) { bx = b1[col]; by = b1[col + 1]; }
        if (row0 < M_ROWS) {
            float2 v = make_float2(d[j][0] + bx, d[j][1] + by);
            *(float2*)(dst + (size_t)row0 * HH + col) = v;
        }
        if (row0 + 8 < M_ROWS) {
            float2 v = make_float2(d[j][2] + bx, d[j][3] + by);
            *(float2*)(dst + (size_t)(row0 + 8) * HH + col) = v;
        }
    }
}

// ---------------------------------------------------------------------------
// Pairwise v4: 64x64 tile, 4x4 outputs/thread (16 ILP chains), h split
// 8-way across blocks -> 256 blocks. Tiles at i0/j0 in {0,36} (36+63=99:
// exact coverage; overlap rows recompute identical values — benign stores).
// Partials to g_part[s]; combine kernel sums + sigmoid.
// ---------------------------------------------------------------------------
#define CH 32
#define PSTR 68      // floats; 68*4=272B (16B-aligned rows), 4-way STS conflict

__global__ __launch_bounds__(256) void pairwise_kernel(const float* __restrict__ W2) {
    __shared__ float sA[CH][PSTR];
    __shared__ float sB[CH][PSTR];
    __shared__ float sW[CH];

    int b = blockIdx.y;
    int bx = blockIdx.x;                 // 0..31
    int s = bx >> 2;                     // h split 0..7
    int i0 = ((bx >> 1) & 1) * 36;       // 0 or 36
    int j0 = (bx & 1) * 36;
    int hbase = s * HSUB;

    int tid = threadIdx.x;
    int ty = tid >> 4, tx = tid & 15;

    float acc[4][4];
    #pragma unroll
    for (int r = 0; r < 4; ++r)
        #pragma unroll
        for (int c = 0; c < 4; ++c) acc[r][c] = 0.f;

    const float* haB = g_ha + (size_t)b * NN * HH;
    const float* hbB = g_hb + (size_t)b * NN * HH;

    for (int hc = 0; hc < HSUB; hc += CH) {
        int h0 = hbase + hc;
        // fill: 64 rows x 32 h per array; coalesced gmem reads
        #pragma unroll
        for (int k = 0; k < 8; ++k) {
            int idx = tid + k * 256;         // 0..2047
            int il = idx >> 5;               // 0..63
            int hl = idx & 31;
            sA[hl][il] = haB[(size_t)(i0 + il) * HH + h0 + hl];
            sB[hl][il] = hbB[(size_t)(j0 + il) * HH + h0 + hl];
        }
        if (tid < CH) sW[tid] = W2[h0 + tid];
        __syncthreads();

        #pragma unroll 8
        for (int h = 0; h < CH; ++h) {
            float4 av = *(const float4*)&sA[h][4 * ty];
            float4 bv = *(const float4*)&sB[h][4 * tx];
            float w = sW[h];
            float ar[4] = {av.x, av.y, av.z, av.w};
            float br[4] = {bv.x, bv.y, bv.z, bv.w};
            #pragma unroll
            for (int r = 0; r < 4; ++r)
                #pragma unroll
                for (int c = 0; c < 4; ++c)
                    acc[r][c] += fmaxf(ar[r] + br[c], 0.f) * w;
        }
        __syncthreads();
    }

    float* dst = g_part + ((size_t)(s * BB + b) * 128) * 128;
    #pragma unroll
    for (int r = 0; r < 4; ++r) {
        int i = i0 + 4 * ty + r;
        float4 v = make_float4(acc[r][0], acc[r][1], acc[r][2], acc[r][3]);
        *(float4*)(dst + (size_t)i * 128 + j0 + 4 * tx) = v;
    }
}

// ---------------------------------------------------------------------------
// Combine: sum 8 partials + b2, sigmoid, write out[b,i,j].
// ---------------------------------------------------------------------------
__global__ void combine_kernel(const float* __restrict__ b2,
                               float* __restrict__ out) {
    int b = blockIdx.y;
    int idx = blockIdx.x * 256 + threadIdx.x;    // 0..10239
    if (idx >= NN * NN) return;
    int i = idx / NN, j = idx % NN;

    float x = b2[0];
    #pragma unroll
    for (int s = 0; s < SPLIT; ++s)
        x += g_part[((size_t)(s * BB + b) * 128 + i) * 128 + j];
    out[((size_t)b * NN + i) * NN + j] = 1.f / (1.f + expf(-x));
}

// ---------------------------------------------------------------------------
// Launch
// ---------------------------------------------------------------------------
extern "C" void kernel_launch(void* const* d_in, const int* in_sizes, int n_in,
                              void* d_out, int out_size) {
    const float* patch_tokens = (const float*)d_in[0];
    const float* boxes        = (const float*)d_in[1];
    const float* W1           = (const float*)d_in[2];
    const float* b1           = (const float*)d_in[3];
    const float* W2           = (const float*)d_in[4];
    const float* b2           = (const float*)d_in[5];
    float* out = (float*)d_out;

    prep_kernel<<<BB * TH + 384, DD>>>(patch_tokens, W1);
    pool_gather_kernel<<<M_ROWS, DD>>>(boxes);

    dim3 ggrid(24, 13);
    gemm_bf16_kernel<<<ggrid, 256>>>(b1);

    dim3 pgrid(32, BB);                          // 256 blocks
    pairwise_kernel<<<pgrid, 256>>>(W2);

    dim3 cgrid((NN * NN + 255) / 256, BB);       // (40, 8)
    combine_kernel<<<cgrid, 256>>>(b2, out);
}

// round 7
// speedup vs baseline: 2.2204x; 1.0452x over previous
#include <cuda_runtime.h>
#include <cuda_bf16.h>
#include <math.h>
#include <stdint.h>

#define BB 8
#define NN 100
#define DD 768
#define HH 768
#define TH 24
#define TT 577
#define IMGF 384.0f
#define M_ROWS 800
#define SPLIT 24
#define HSUB (HH / SPLIT)    // 32

// Scratch (device globals: allocation-free, graph-capture safe)
__device__ float g_rowsum[BB * TH * TH * DD];
__device__ __nv_bfloat16 g_pA[M_ROWS * DD];
__device__ __nv_bfloat16 g_pW[2 * DD * HH];
__device__ float g_ha[M_ROWS * HH];                 // pooled@W1[:D] + b1
__device__ float g_hb[M_ROWS * HH];                 // pooled@W1[D:]
__device__ float g_part[SPLIT * BB * NN * NN];      // pairwise partials, 7.7MB

// ---------------------------------------------------------------------------
// Kernel A (fused): blocks 0..191 row-prefix-sum the feature map;
// blocks 192..575 convert W1 fp32 -> bf16.
// ---------------------------------------------------------------------------
__global__ void prep_kernel(const float* __restrict__ tokens,
                            const float* __restrict__ W1) {
    if (blockIdx.x < BB * TH) {
        int by = blockIdx.x;
        int b = by / TH, y = by % TH;
        int t = threadIdx.x;
        const float* src = tokens + ((size_t)b * TT + 1 + y * TH) * DD + t;
        float* dst = g_rowsum + ((size_t)(b * TH + y) * TH) * DD + t;
        float run = 0.f;
        #pragma unroll
        for (int x = 0; x < TH; ++x) {
            run += src[(size_t)x * DD];
            dst[(size_t)x * DD] = run;
        }
    } else {
        int i = (blockIdx.x - BB * TH) * 768 + threadIdx.x;
        float4 v = ((const float4*)W1)[i];
        __nv_bfloat162* dst = (__nv_bfloat162*)(g_pW + (size_t)i * 4);
        dst[0] = __floats2bfloat162_rn(v.x, v.y);
        dst[1] = __floats2bfloat162_rn(v.z, v.w);
    }
}

// ---------------------------------------------------------------------------
// Kernel B: ROI pool from row-prefix sums -> pooled bf16.
// ---------------------------------------------------------------------------
__device__ __forceinline__ int to_patch(float v) {
    float pix = floorf(v * IMGF);
    return (int)floorf(pix / IMGF * (float)TH);
}

__global__ void pool_gather_kernel(const float* __restrict__ boxes) {
    int bn = blockIdx.x;
    int b = bn / NN;
    const float* box = boxes + (size_t)bn * 4;

    int px1 = min(max(to_patch(box[0]), 0), TH - 1);
    int py1 = min(max(to_patch(box[1]), 0), TH - 1);
    int px2 = min(max(to_patch(box[2]), 1), TH);
    int py2 = min(max(to_patch(box[3]), 1), TH);
    if (px2 <= px1) px2 = px1 + 1;
    if (py2 <= py1) py2 = py1 + 1;

    float inv = 1.0f / (float)((px2 - px1) * (py2 - py1));

    int t = threadIdx.x;
    const float* base = g_rowsum + (size_t)(b * TH * TH) * DD + t;
    float s = 0.f;
    for (int y = py1; y < py2; ++y) {
        const float* row = base + (size_t)(y * TH) * DD;
        float hi = row[(size_t)(px2 - 1) * DD];
        float lo = (px1 > 0) ? row[(size_t)(px1 - 1) * DD] : 0.f;
        s += hi - lo;
    }
    g_pA[(size_t)bn * DD + t] = __float2bfloat16_rn(s * inv);
}

// ---------------------------------------------------------------------------
// bf16 tensor-core GEMM: C[800,1536] = pooled[800,768] @ W[768,1536]
// cols 0-767 -> g_ha (+b1 fused), 768-1535 -> g_hb.
// ---------------------------------------------------------------------------
#define ASTR 40
#define BSTR 72

__global__ __launch_bounds__(256) void gemm_bf16_kernel(const float* __restrict__ b1) {
    __shared__ __nv_bfloat16 As[2][64 * ASTR];
    __shared__ __nv_bfloat16 Bs[2][32 * BSTR];

    int tid = threadIdx.x;
    int lane = tid & 31, wid = tid >> 5;
    int m0 = blockIdx.y * 64;
    int nblk = blockIdx.x;
    int half = (nblk >= 12);
    int n_in0 = nblk * 64 - half * 768;
    const __nv_bfloat16* Bg = g_pW + (size_t)half * DD * HH;

    int a_r = tid >> 2, a_c = (tid & 3) * 8;
    int b_r = tid >> 3, b_c = (tid & 7) * 8;
    int wm = (wid & 3) * 16, wn = (wid >> 2) * 32;

    float d[4][4];
    #pragma unroll
    for (int j = 0; j < 4; ++j)
        #pragma unroll
        for (int c = 0; c < 4; ++c) d[j][c] = 0.f;

    const uint4 z4 = make_uint4(0, 0, 0, 0);
    uint4 ra, rb;

    {
        int gr = m0 + a_r;
        ra = (gr < M_ROWS) ? *(const uint4*)(g_pA + (size_t)gr * DD + a_c) : z4;
        rb = *(const uint4*)(Bg + (size_t)b_r * HH + n_in0 + b_c);
        *(uint4*)(As[0] + a_r * ASTR + a_c) = ra;
        *(uint4*)(Bs[0] + b_r * BSTR + b_c) = rb;
    }
    __syncthreads();

    int lrow = (lane & 7) + ((lane >> 3) & 1) * 8;
    int lk8  = (lane >> 4) * 8;

    for (int it = 0; it < 24; ++it) {
        int buf = it & 1;
        if (it < 23) {
            int k0 = (it + 1) * 32;
            int gr = m0 + a_r;
            ra = (gr < M_ROWS) ? *(const uint4*)(g_pA + (size_t)gr * DD + k0 + a_c) : z4;
            rb = *(const uint4*)(Bg + (size_t)(k0 + b_r) * HH + n_in0 + b_c);
        }
        uint32_t abase = (uint32_t)__cvta_generic_to_shared(&As[buf][0]);
        uint32_t bbase = (uint32_t)__cvta_generic_to_shared(&Bs[buf][0]);

        #pragma unroll
        for (int kq = 0; kq < 32; kq += 16) {
            uint32_t a0, a1, a2, a3;
            uint32_t aaddr = abase + (uint32_t)(((wm + lrow) * ASTR + kq + lk8) * 2);
            asm volatile("ldmatrix.sync.aligned.m8n8.x4.shared.b16 {%0,%1,%2,%3}, [%4];"
                         : "=r"(a0), "=r"(a1), "=r"(a2), "=r"(a3) : "r"(aaddr));
            #pragma unroll
            for (int h = 0; h < 2; ++h) {
                uint32_t b0, b1r, b2, b3;
                uint32_t baddr = bbase + (uint32_t)(((kq + lrow) * BSTR + wn + h * 16 + lk8) * 2);
                asm volatile("ldmatrix.sync.aligned.m8n8.x4.trans.shared.b16 {%0,%1,%2,%3}, [%4];"
                             : "=r"(b0), "=r"(b1r), "=r"(b2), "=r"(b3) : "r"(baddr));
                asm volatile("mma.sync.aligned.m16n8k16.row.col.f32.bf16.bf16.f32 "
                             "{%0,%1,%2,%3}, {%4,%5,%6,%7}, {%8,%9}, {%0,%1,%2,%3};"
                             : "+f"(d[2*h][0]), "+f"(d[2*h][1]), "+f"(d[2*h][2]), "+f"(d[2*h][3])
                             : "r"(a0), "r"(a1), "r"(a2), "r"(a3), "r"(b0), "r"(b1r));
                asm volatile("mma.sync.aligned.m16n8k16.row.col.f32.bf16.bf16.f32 "
                             "{%0,%1,%2,%3}, {%4,%5,%6,%7}, {%8,%9}, {%0,%1,%2,%3};"
                             : "+f"(d[2*h+1][0]), "+f"(d[2*h+1][1]), "+f"(d[2*h+1][2]), "+f"(d[2*h+1][3])
                             : "r"(a0), "r"(a1), "r"(a2), "r"(a3), "r"(b2), "r"(b3));
            }
        }
        if (it < 23) {
            *(uint4*)(As[buf ^ 1] + a_r * ASTR + a_c) = ra;
            *(uint4*)(Bs[buf ^ 1] + b_r * BSTR + b_c) = rb;
            __syncthreads();
        }
    }

    float* dst = half ? g_hb : g_ha;
    int row0 = m0 + wm + (lane >> 2);
    #pragma unroll
    for (int j = 0; j < 4; ++j) {
        int col = n_in0 + wn + j * 8 + (lane & 3) * 2;
        float bx = 0.f, by = 0.f;
        if (!half) { bx = b1[col]; by = b1[col + 1]; }
        if (row0 < M_ROWS) {
            float2 v = make_float2(d[j][0] + bx, d[j][1] + by);
            *(float2*)(dst + (size_t)row0 * HH + col) = v;
        }
        if (row0 + 8 < M_ROWS) {
            float2 v = make_float2(d[j][2] + bx, d[j][3] + by);
            *(float2*)(dst + (size_t)(row0 + 8) * HH + col) = v;
        }
    }
}

// ---------------------------------------------------------------------------
// Pairwise v5: exact coverage. One block = full 100x100 output for one
// (h-split, batch). 500 threads (ty 0..19 x tx 0..24), each owns 5x4 outputs.
// Each block processes exactly HSUB=32 h values (single smem fill, one sync).
// Inner-loop smem reads: av = 5 broadcast LDS (all lanes share h row),
// bv = LDS.128; zero padding waste, 20 ILP chains/thread.
// ---------------------------------------------------------------------------
__global__ __launch_bounds__(512, 2) void pairwise_kernel(const float* __restrict__ W2) {
    __shared__ float sA[HSUB][NN];
    __shared__ float sB[HSUB][NN];
    __shared__ float sW[HSUB];

    int s = blockIdx.x;                  // 0..23 (h split)
    int b = blockIdx.y;
    int hbase = s * HSUB;

    int tid = threadIdx.x;               // 0..499
    int ty = tid / 25;                   // 0..19  (i:  rows 5*ty..5*ty+4)
    int tx = tid % 25;                   // 0..24  (j:  cols 4*tx..4*tx+3)

    const float* haB = g_ha + ((size_t)b * NN) * HH + hbase;
    const float* hbB = g_hb + ((size_t)b * NN) * HH + hbase;

    // fill: 100 rows x 32 h per array (3200 elems, 500 threads -> 7 iters)
    for (int idx = tid; idx < NN * HSUB; idx += 500) {
        int row = idx / HSUB, hl = idx % HSUB;      // consecutive idx -> consecutive hl
        sA[hl][row] = haB[(size_t)row * HH + hl];
        sB[hl][row] = hbB[(size_t)row * HH + hl];
    }
    if (tid < HSUB) sW[tid] = W2[hbase + tid];
    __syncthreads();

    float acc[5][4];
    #pragma unroll
    for (int r = 0; r < 5; ++r)
        #pragma unroll
        for (int c = 0; c < 4; ++c) acc[r][c] = 0.f;

    #pragma unroll 4
    for (int h = 0; h < HSUB; ++h) {
        float w = sW[h];
        float ar[5];
        #pragma unroll
        for (int r = 0; r < 5; ++r) ar[r] = sA[h][5 * ty + r];
        float4 bv = *(const float4*)&sB[h][4 * tx];
        float br[4] = {bv.x, bv.y, bv.z, bv.w};
        #pragma unroll
        for (int r = 0; r < 5; ++r)
            #pragma unroll
            for (int c = 0; c < 4; ++c)
                acc[r][c] += fmaxf(ar[r] + br[c], 0.f) * w;
    }

    float* dst = g_part + ((size_t)(s * BB + b) * NN) * NN;
    #pragma unroll
    for (int r = 0; r < 5; ++r) {
        float4 v = make_float4(acc[r][0], acc[r][1], acc[r][2], acc[r][3]);
        *(float4*)(dst + (size_t)(5 * ty + r) * NN + 4 * tx) = v;
    }
}

// ---------------------------------------------------------------------------
// Combine: sum 24 partials + b2, sigmoid, write out[b,i,j].
// ---------------------------------------------------------------------------
__global__ void combine_kernel(const float* __restrict__ b2,
                               float* __restrict__ out) {
    int b = blockIdx.y;
    int idx = blockIdx.x * 256 + threadIdx.x;
    if (idx >= NN * NN) return;

    float x = b2[0];
    #pragma unroll
    for (int s = 0; s < SPLIT; ++s)
        x += g_part[((size_t)(s * BB + b) * NN * NN) + idx];
    out[(size_t)b * NN * NN + idx] = 1.f / (1.f + expf(-x));
}

// ---------------------------------------------------------------------------
// Launch
// ---------------------------------------------------------------------------
extern "C" void kernel_launch(void* const* d_in, const int* in_sizes, int n_in,
                              void* d_out, int out_size) {
    const float* patch_tokens = (const float*)d_in[0];
    const float* boxes        = (const float*)d_in[1];
    const float* W1           = (const float*)d_in[2];
    const float* b1           = (const float*)d_in[3];
    const float* W2           = (const float*)d_in[4];
    const float* b2           = (const float*)d_in[5];
    float* out = (float*)d_out;

    prep_kernel<<<BB * TH + 384, DD>>>(patch_tokens, W1);
    pool_gather_kernel<<<M_ROWS, DD>>>(boxes);

    dim3 ggrid(24, 13);
    gemm_bf16_kernel<<<ggrid, 256>>>(b1);

    dim3 pgrid(SPLIT, BB);                       // 192 blocks
    pairwise_kernel<<<pgrid, 500>>>(W2);

    dim3 cgrid((NN * NN + 255) / 256, BB);       // (40, 8)
    combine_kernel<<<cgrid, 256>>>(b2, out);
}